// round 8
// baseline (speedup 1.0000x reference)
#include <cuda_runtime.h>
#include <cuda_bf16.h>
#include <math.h>

// EMA with SD — fused decoupled-lookback, r4 store shape (round 8).
// x (T=8192, D=128); h_a0, h_sd0, alpha (N=32, D=128).
// out: (T, 2N, D) fp32, then hN_a (N,D), hN_sd (N,D).
//
// C=64 chunks of L=128. Block (c,n) = 64 threads, float2 lanes (r4's proven
// 4.3TB/s store config, 4096 warps co-resident).
//   Phase A: chunk summary  P = g[L-1],  A = sum beta^{L-1-i}*beta*alpha*u_i^2
//            (S is redundant: S = P/alpha)
//   publish (threadfence + flag), fold predecessors:
//     W = beta^128 (squaring), C = W(1-W), B = -2*W*P
//     hv' = W*hv + C*ha^2 + B*ha + A ; ha' = W*ha + P
//   Phase C: exact replay, streaming float2 stores.

#define TT 8192
#define DD 128
#define NN 32
#define CC 64
#define LL 128
#define LANES (NN * DD)

__device__ float g_P[CC * LANES];
__device__ float g_A[CC * LANES];
__device__ int   g_flag[CC * NN];

__device__ __forceinline__ float sqrt_fast(float v) {
    float r;
    asm("sqrt.approx.f32 %0, %1;" : "=f"(r) : "f"(v));
    return r;
}

__device__ __forceinline__ int ld_vol(const int* p) {
    int v;
    asm volatile("ld.volatile.global.s32 %0, [%1];" : "=r"(v) : "l"(p));
    return v;
}

__global__ __launch_bounds__(64, 14) void ema_fused(
    const float* __restrict__ x,
    const float* __restrict__ h_a0,
    const float* __restrict__ h_sd0,
    const float* __restrict__ alpha,
    float* __restrict__ out,
    int write_tail)
{
    const int n = blockIdx.x;            // 0..31
    const int c = blockIdx.y;            // 0..63
    const int t = threadIdx.x;           // 0..63
    const int idx = n * DD + 2 * t;      // even lane index

    const float2 al = *reinterpret_cast<const float2*>(alpha + idx);
    const float a0 = al.x, a1 = al.y;
    const float b0 = 1.0f - a0, b1 = 1.0f - a1;

    const float2* xp = reinterpret_cast<const float2*>(x + (size_t)c * LL * DD + 2 * t);

    // ---------------- Phase A: own-chunk summary ----------------
    float g0 = 0.f, g1 = 0.f, A0 = 0.f, A1 = 0.f;

#pragma unroll 8
    for (int i = 0; i < LL; ++i) {
        const float2 xv = xp[(size_t)i * (DD / 2)];
        const float u0 = xv.x - g0;
        const float u1 = xv.y - g1;
        g0 = fmaf(a0, u0, g0);
        g1 = fmaf(a1, u1, g1);
        A0 = b0 * fmaf(a0, u0 * u0, A0);
        A1 = b1 * fmaf(a1, u1 * u1, A1);
    }

    const int s = c * LANES + idx;
    *reinterpret_cast<float2*>(g_P + s) = make_float2(g0, g1);
    *reinterpret_cast<float2*>(g_A + s) = make_float2(A0, A1);
    __threadfence();
    __syncthreads();
    if (t == 0) atomicExch(&g_flag[c * NN + n], 1);

    // ---------------- per-lane fold constants ----------------
    float W0, W1;
    {
        float p = b0 * b0; p *= p; p *= p; p *= p; p *= p; p *= p; W0 = p * p; // b0^128
    }
    {
        float p = b1 * b1; p *= p; p *= p; p *= p; p *= p; p *= p; W1 = p * p; // b1^128
    }
    const float Cq0 = W0 * (1.0f - W0), Cq1 = W1 * (1.0f - W1);
    const float m2W0 = -2.0f * W0,      m2W1 = -2.0f * W1;

    // ---------------- Phase B: fold predecessors ----------------
    const float2 hav = *reinterpret_cast<const float2*>(h_a0 + idx);
    const float2 sdv = *reinterpret_cast<const float2*>(h_sd0 + idx);
    float ha0 = hav.x, ha1 = hav.y;
    float hv0 = sdv.x * sdv.x, hv1 = sdv.y * sdv.y;

    for (int cc = 0; cc < c; ++cc) {
        const int fi = cc * NN + n;
        while (ld_vol(&g_flag[fi]) == 0) { }
        __threadfence();                    // acquire
        const int sb = cc * LANES + idx;
        const float2 P = *reinterpret_cast<const float2*>(g_P + sb);
        const float2 Aa = *reinterpret_cast<const float2*>(g_A + sb);
        float hvn;
        hvn = fmaf(W0, hv0, fmaf(Cq0, ha0 * ha0, fmaf(m2W0 * P.x, ha0, Aa.x)));
        hv0 = fmaxf(hvn, 0.f);
        ha0 = fmaf(W0, ha0, P.x);
        hvn = fmaf(W1, hv1, fmaf(Cq1, ha1 * ha1, fmaf(m2W1 * P.y, ha1, Aa.y)));
        hv1 = fmaxf(hvn, 0.f);
        ha1 = fmaf(W1, ha1, P.y);
    }

    // ---------------- Phase C: exact replay (r4 store shape) ----------------
    float2* obase = reinterpret_cast<float2*>(out + (size_t)c * LL * (2 * NN * DD) + idx);

#pragma unroll 8
    for (int i = 0; i < LL; ++i) {
        const float2 xv = xp[(size_t)i * (DD / 2)];
        const float u0 = xv.x - ha0;
        const float u1 = xv.y - ha1;
        ha0 = fmaf(a0, u0, ha0);
        ha1 = fmaf(a1, u1, ha1);
        hv0 = b0 * fmaf(a0, u0 * u0, hv0);
        hv1 = b1 * fmaf(a1, u1 * u1, hv1);
        float2* op = obase + (size_t)i * (NN * DD);      // i * 4096 float2
        __stcs(op, make_float2(ha0, ha1));
        __stcs(op + (NN * DD / 2), make_float2(sqrt_fast(hv0), sqrt_fast(hv1)));
    }

    // ---------------- tail: final states ----------------
    if (write_tail && c == CC - 1) {
        const size_t base = (size_t)TT * 2 * NN * DD;
        *reinterpret_cast<float2*>(out + base + idx) = make_float2(ha0, ha1);
        *reinterpret_cast<float2*>(out + base + LANES + idx) =
            make_float2(sqrt_fast(hv0), sqrt_fast(hv1));
    }
}

extern "C" void kernel_launch(void* const* d_in, const int* in_sizes, int n_in,
                              void* d_out, int out_size)
{
    const float* x     = (const float*)d_in[0];
    const float* h_a0  = (const float*)d_in[1];
    const float* h_sd0 = (const float*)d_in[2];
    const float* alpha = (const float*)d_in[3];
    float* out = (float*)d_out;

    const int main_elems = TT * 2 * NN * DD;
    const int write_tail = (out_size > main_elems) ? 1 : 0;

    void* flag_ptr = nullptr;
    cudaGetSymbolAddress(&flag_ptr, g_flag);
    cudaMemsetAsync(flag_ptr, 0, CC * NN * sizeof(int));

    dim3 grid(NN, CC);
    ema_fused<<<grid, 64>>>(x, h_a0, h_sd0, alpha, out, write_tail);
}

// round 9
// speedup vs baseline: 1.2116x; 1.2116x over previous
#include <cuda_runtime.h>
#include <cuda_bf16.h>
#include <math.h>

// EMA with SD, chunked parallel scan (round 9).
// x (T=8192, D=128); h_a0, h_sd0, alpha (N=32, D=128).
// out: (T, 2N, D) fp32, then hN_a (N,D), hN_sd (N,D).
//
// pass1: CS=128 chunks of LS=64, each thread runs TWO independent 32-step
//        sub-streams (2x MLP) and merges them exactly:
//          W' = W^2, P' = W*P0 + P1,
//          A' = W*A0 + A1 + W*(1-W)*P0^2 - 2*W*P0*P1
//        (quadratic-map composition; B == -2*W*P is implied, no S array)
// combine: folds 128 summaries per lane with W=b^64:
//          hv' = W*hv + W(1-W)*ha^2 - 2W*P*ha + A ; ha' = W*ha + P
//          writes replay entry states at even chunks (CR=64).
// pass2: EXACT round-4 shape (float2 lanes, CC=64, L=128, __stcs streaming
//        stores, sqrt.approx) — measured 62us, empirical store-wall optimum.

#define TT 8192
#define DD 128
#define NN 32
#define CS 128
#define LS 64
#define HS 32           // LS/2 sub-stream length
#define CR 64
#define LR 128
#define LANES (NN * DD)

__device__ float g_P  [CS * LANES];
__device__ float g_A  [CS * LANES];
__device__ float g_ha0[CR * LANES];
__device__ float g_hv0[CR * LANES];

__device__ __forceinline__ float sqrt_fast(float v) {
    float r;
    asm("sqrt.approx.f32 %0, %1;" : "=f"(r) : "f"(v));
    return r;
}

// ---------------------------------------------------------------- pass 1
__global__ __launch_bounds__(64) void ema_pass1(
    const float* __restrict__ x,
    const float* __restrict__ alpha)
{
    const int c  = blockIdx.x;           // 0..CS-1
    const int n  = blockIdx.y;           // 0..NN-1
    const int t  = threadIdx.x;          // 0..63
    const int idx = n * DD + 2 * t;

    const float2 al = *reinterpret_cast<const float2*>(alpha + idx);
    const float a0 = al.x, a1 = al.y;
    const float b0 = 1.0f - a0, b1 = 1.0f - a1;

    const float2* xp0 = reinterpret_cast<const float2*>(x + (size_t)c * LS * DD + 2 * t);
    const float2* xp1 = xp0 + (size_t)HS * (DD / 2);

    // Two independent sub-streams (s0: steps 0..31, s1: steps 32..63)
    float g0a = 0.f, g0b = 0.f, A0a = 0.f, A0b = 0.f;   // stream 0
    float g1a = 0.f, g1b = 0.f, A1a = 0.f, A1b = 0.f;   // stream 1

#pragma unroll 8
    for (int i = 0; i < HS; ++i) {
        const float2 x0 = xp0[(size_t)i * (DD / 2)];
        const float2 x1 = xp1[(size_t)i * (DD / 2)];
        const float u0a = x0.x - g0a, u0b = x0.y - g0b;
        const float u1a = x1.x - g1a, u1b = x1.y - g1b;
        g0a = fmaf(a0, u0a, g0a);
        g0b = fmaf(a1, u0b, g0b);
        g1a = fmaf(a0, u1a, g1a);
        g1b = fmaf(a1, u1b, g1b);
        A0a = b0 * fmaf(a0, u0a * u0a, A0a);
        A0b = b1 * fmaf(a1, u0b * u0b, A0b);
        A1a = b0 * fmaf(a0, u1a * u1a, A1a);
        A1b = b1 * fmaf(a1, u1b * u1b, A1b);
    }

    // Exact merge of the two 32-step summaries into one 64-step summary.
    float W0, W1;   // b^32 per lane
    {
        float p = b0 * b0; p *= p; p *= p; p *= p; W0 = p * p;   // b0^32
    }
    {
        float p = b1 * b1; p *= p; p *= p; p *= p; W1 = p * p;   // b1^32
    }
    // P' = W*P0 + P1
    const float Pm0 = fmaf(W0, g0a, g1a);
    const float Pm1 = fmaf(W1, g0b, g1b);
    // A' = W*A0 + A1 + W*(1-W)*P0^2 - 2*W*P0*P1
    const float Am0 = fmaf(W0, A0a, A1a)
                    + W0 * fmaf((1.0f - W0) * g0a, g0a, -2.0f * g0a * g1a);
    const float Am1 = fmaf(W1, A0b, A1b)
                    + W1 * fmaf((1.0f - W1) * g0b, g0b, -2.0f * g0b * g1b);

    const int s = c * LANES + idx;
    *reinterpret_cast<float2*>(g_P + s) = make_float2(Pm0, Pm1);
    *reinterpret_cast<float2*>(g_A + s) = make_float2(Am0, Am1);
}

// ---------------------------------------------------------------- combine
__global__ __launch_bounds__(DD) void ema_combine(
    const float* __restrict__ h_a0,
    const float* __restrict__ h_sd0,
    const float* __restrict__ alpha,
    float* __restrict__ out,
    int write_tail)
{
    const int n = blockIdx.x;
    const int d = threadIdx.x;
    const int idx = n * DD + d;

    const float a = alpha[idx];
    const float b = 1.0f - a;
    float W;   // b^64
    {
        float p = b * b; p *= p; p *= p; p *= p; p *= p; W = p * p;
    }
    const float Cq  = W * (1.0f - W);
    const float m2W = -2.0f * W;

    float ha = h_a0[idx];
    const float sd = h_sd0[idx];
    float hv = sd * sd;

#pragma unroll 8
    for (int c = 0; c < CS; ++c) {
        if ((c & 1) == 0) {
            const int e = (c >> 1) * LANES + idx;
            g_ha0[e] = ha;
            g_hv0[e] = hv;
        }
        const int s = c * LANES + idx;
        const float P = g_P[s];
        const float A = g_A[s];
        const float hv_new = fmaf(W, hv, fmaf(Cq, ha * ha, fmaf(m2W * P, ha, A)));
        hv = fmaxf(hv_new, 0.0f);
        ha = fmaf(W, ha, P);
    }

    if (write_tail) {
        const size_t base = (size_t)TT * 2 * NN * DD;
        out[base + idx]         = ha;          // hN_a
        out[base + LANES + idx] = sqrtf(hv);   // hN_sd
    }
}

// ---------------------------------------------------------------- pass 2
// EXACT round-4 shape: float2 lanes, 64-thread blocks, grid (CR, NN),
// streaming stores. Measured 62us.
__global__ __launch_bounds__(64) void ema_pass2(
    const float* __restrict__ x,
    const float* __restrict__ alpha,
    float* __restrict__ out)
{
    const int c  = blockIdx.x;           // 0..CR-1
    const int n  = blockIdx.y;           // 0..NN-1
    const int d2 = threadIdx.x;          // 0..63
    const int idx = n * DD + 2 * d2;

    const float2 al = *reinterpret_cast<const float2*>(alpha + idx);
    const float a0 = al.x, a1 = al.y;
    const float b0 = 1.0f - a0, b1 = 1.0f - a1;

    const int s = c * LANES + idx;
    const float2 hav = *reinterpret_cast<const float2*>(g_ha0 + s);
    const float2 hvv = *reinterpret_cast<const float2*>(g_hv0 + s);
    float ha0 = hav.x, ha1 = hav.y;
    float hv0 = hvv.x, hv1 = hvv.y;

    const float2* xp = reinterpret_cast<const float2*>(x + (size_t)c * LR * DD + 2 * d2);
    float2* obase = reinterpret_cast<float2*>(out + (size_t)c * LR * 2 * NN * DD + n * DD + 2 * d2);

#pragma unroll 8
    for (int i = 0; i < LR; ++i) {
        const float2 xv = xp[(size_t)i * (DD / 2)];
        const float u0 = xv.x - ha0;
        const float u1 = xv.y - ha1;
        ha0 = fmaf(a0, u0, ha0);
        ha1 = fmaf(a1, u1, ha1);
        hv0 = b0 * fmaf(a0, u0 * u0, hv0);
        hv1 = b1 * fmaf(a1, u1 * u1, hv1);
        float2* op = obase + (size_t)i * (NN * DD);      // i * 4096 float2
        __stcs(op, make_float2(ha0, ha1));
        __stcs(op + (NN * DD / 2), make_float2(sqrt_fast(hv0), sqrt_fast(hv1)));
    }
}

extern "C" void kernel_launch(void* const* d_in, const int* in_sizes, int n_in,
                              void* d_out, int out_size)
{
    const float* x     = (const float*)d_in[0];
    const float* h_a0  = (const float*)d_in[1];
    const float* h_sd0 = (const float*)d_in[2];
    const float* alpha = (const float*)d_in[3];
    float* out = (float*)d_out;

    const int main_elems = TT * 2 * NN * DD;
    const int write_tail = (out_size > main_elems) ? 1 : 0;

    dim3 grid1(CS, NN);
    ema_pass1<<<grid1, 64>>>(x, alpha);
    ema_combine<<<NN, DD>>>(h_a0, h_sd0, alpha, out, write_tail);
    dim3 grid2(CR, NN);
    ema_pass2<<<grid2, 64>>>(x, alpha, out);
}